// round 1
// baseline (speedup 1.0000x reference)
#include <cuda_runtime.h>
#include <cuda_bf16.h>
#include <cstdint>

// Fixed problem shapes (MoELayer: B=2,S=2048,H=2048,I=4096,E=8, top-2)
#define TT 4096   // tokens = B*S
#define HH 2048   // hidden
#define II 4096   // intermediate
#define EE 8      // experts
#define NASG (2*TT)  // total assignments (top-2) == 8192 always

#define BM 128
#define BN 128
#define BK 32
#define APAD 8
#define BPAD 8

// ---------------- static device scratch (no allocation allowed) --------------
__device__ int   g_cnt[EE];
__device__ int   g_off[EE];
__device__ int   g_tok[EE * TT];        // per-expert token lists (slot -> token)
__device__ int   g_asg[TT * 2];         // per token: (e<<12)|slot for its 2 experts
__device__ float g_wt[TT * 2];          // per token: renormalized top-2 weights
__device__ float g_hg[(size_t)NASG * II];   // gate GEMM out
__device__ float g_hu[(size_t)NASG * II];   // up GEMM out
__device__ float g_h [(size_t)NASG * II];   // swiglu out (A of down GEMM)
__device__ float g_y [(size_t)NASG * HH];   // down GEMM out

// ---------------- helpers ----------------------------------------------------
__device__ __forceinline__ void ldm4(uint32_t* r, const __nv_bfloat16* p) {
    uint32_t a = (uint32_t)__cvta_generic_to_shared(p);
    asm volatile("ldmatrix.sync.aligned.m8n8.x4.shared.b16 {%0,%1,%2,%3}, [%4];"
                 : "=r"(r[0]), "=r"(r[1]), "=r"(r[2]), "=r"(r[3]) : "r"(a));
}
__device__ __forceinline__ void ldm4t(uint32_t* r, const __nv_bfloat16* p) {
    uint32_t a = (uint32_t)__cvta_generic_to_shared(p);
    asm volatile("ldmatrix.sync.aligned.m8n8.x4.trans.shared.b16 {%0,%1,%2,%3}, [%4];"
                 : "=r"(r[0]), "=r"(r[1]), "=r"(r[2]), "=r"(r[3]) : "r"(a));
}
__device__ __forceinline__ void mma16816(float* c, const uint32_t* a, const uint32_t* b) {
    asm volatile("mma.sync.aligned.m16n8k16.row.col.f32.bf16.bf16.f32 "
                 "{%0,%1,%2,%3},{%4,%5,%6,%7},{%8,%9},{%0,%1,%2,%3};"
                 : "+f"(c[0]), "+f"(c[1]), "+f"(c[2]), "+f"(c[3])
                 : "r"(a[0]), "r"(a[1]), "r"(a[2]), "r"(a[3]), "r"(b[0]), "r"(b[1]));
}
// split fp32 -> hi/lo bf16 and store 4 elements to each plane (8B stores)
__device__ __forceinline__ void cvtstore4(__nv_bfloat16* hp, __nv_bfloat16* lp, float4 v) {
    __nv_bfloat16 h0 = __float2bfloat16_rn(v.x);
    __nv_bfloat16 h1 = __float2bfloat16_rn(v.y);
    __nv_bfloat16 h2 = __float2bfloat16_rn(v.z);
    __nv_bfloat16 h3 = __float2bfloat16_rn(v.w);
    __nv_bfloat16 l0 = __float2bfloat16_rn(v.x - __bfloat162float(h0));
    __nv_bfloat16 l1 = __float2bfloat16_rn(v.y - __bfloat162float(h1));
    __nv_bfloat16 l2 = __float2bfloat16_rn(v.z - __bfloat162float(h2));
    __nv_bfloat16 l3 = __float2bfloat16_rn(v.w - __bfloat162float(h3));
    __nv_bfloat162 a, b;
    a.x = h0; a.y = h1; b.x = h2; b.y = h3;
    ((__nv_bfloat162*)hp)[0] = a; ((__nv_bfloat162*)hp)[1] = b;
    a.x = l0; a.y = l1; b.x = l2; b.y = l3;
    ((__nv_bfloat162*)lp)[0] = a; ((__nv_bfloat162*)lp)[1] = b;
}

// ---------------- kernels ----------------------------------------------------
__global__ void zero_cnt_kernel() {
    if (threadIdx.x < EE) g_cnt[threadIdx.x] = 0;
}

// One block per token: logits = x_t @ gate_w, softmax, top-2, renorm, assign slots.
__global__ void router_kernel(const float* __restrict__ x, const float* __restrict__ gw) {
    int t = blockIdx.x;
    const float* xr = x + (size_t)t * HH;
    __shared__ float slog[EE];
    int warp = threadIdx.x >> 5, lane = threadIdx.x & 31;  // 8 warps, warp e -> expert e
    float s = 0.f;
    for (int h = lane; h < HH; h += 32) s += xr[h] * gw[h * EE + warp];
    #pragma unroll
    for (int o = 16; o; o >>= 1) s += __shfl_xor_sync(0xffffffffu, s, o);
    if (lane == 0) slog[warp] = s;
    __syncthreads();
    if (threadIdx.x == 0) {
        float mx = slog[0];
        #pragma unroll
        for (int e = 1; e < EE; e++) mx = fmaxf(mx, slog[e]);
        float p[EE];
        #pragma unroll
        for (int e = 0; e < EE; e++) p[e] = __expf(slog[e] - mx);
        // top-2 (ties -> lower index first, matching lax.top_k)
        int i0 = 0;
        #pragma unroll
        for (int e = 1; e < EE; e++) if (p[e] > p[i0]) i0 = e;
        int i1 = (i0 == 0) ? 1 : 0;
        #pragma unroll
        for (int e = 0; e < EE; e++) if (e != i0 && p[e] > p[i1]) i1 = e;
        float w0 = p[i0], w1 = p[i1], ws = w0 + w1;
        w0 /= ws; w1 /= ws;                    // softmax denom cancels in renorm
        int s0 = atomicAdd(&g_cnt[i0], 1);
        int s1 = atomicAdd(&g_cnt[i1], 1);
        g_tok[i0 * TT + s0] = t;
        g_tok[i1 * TT + s1] = t;
        g_asg[t * 2 + 0] = (i0 << 12) | s0;  g_wt[t * 2 + 0] = w0;
        g_asg[t * 2 + 1] = (i1 << 12) | s1;  g_wt[t * 2 + 1] = w1;
    }
}

__global__ void prefix_kernel() {
    if (threadIdx.x == 0) {
        int a = 0;
        #pragma unroll
        for (int e = 0; e < EE; e++) { g_off[e] = a; a += g_cnt[e]; }
    }
}

// Split-bf16 emulated-fp32 GEMM: C[offe+m][n] = A_rows @ Bw[e]  (fp32 in/out)
// GATHER: A row m = x[g_tok[e*TT+m]] ; else A row m = A[(offe+m)]
template <bool GATHER>
__global__ __launch_bounds__(256) void gemm_kernel(
    const float* __restrict__ A, const float* __restrict__ Bw,
    float* __restrict__ C, int K, int N)
{
    int e = blockIdx.z;
    int Me = g_cnt[e];
    int m0blk = blockIdx.y * BM;
    if (m0blk >= Me) return;
    int offe = g_off[e];
    const float* Bp = Bw + (size_t)e * K * N + (size_t)blockIdx.x * BN;

    __shared__ __align__(16) __nv_bfloat16 Ah[BM * (BK + APAD)];
    __shared__ __align__(16) __nv_bfloat16 Al[BM * (BK + APAD)];
    __shared__ __align__(16) __nv_bfloat16 Bh[BK * (BN + BPAD)];
    __shared__ __align__(16) __nv_bfloat16 Bl[BK * (BN + BPAD)];

    int tid = threadIdx.x;
    int lane = tid & 31, warp = tid >> 5;
    int wm = (warp & 1) * 64;        // 2 warps in M
    int wn = (warp >> 1) * 32;       // 4 warps in N

    float acc[4][4][4];
    #pragma unroll
    for (int mt = 0; mt < 4; mt++)
        #pragma unroll
        for (int nt = 0; nt < 4; nt++)
            #pragma unroll
            for (int i = 0; i < 4; i++) acc[mt][nt][i] = 0.f;

    // Per-thread A-load plan: 4 float4s, row = (tid+i*256)>>3, col4 = (tid+i*256)&7
    const float* arow[4];
    int acol[4], ar[4];
    #pragma unroll
    for (int i = 0; i < 4; i++) {
        int id = tid + i * 256;
        ar[i] = id >> 3;
        acol[i] = (id & 7) * 4;
        int gm = m0blk + ar[i];
        if (gm < Me) {
            if (GATHER) arow[i] = A + (size_t)g_tok[e * TT + gm] * K;
            else        arow[i] = A + (size_t)(offe + gm) * K;
        } else arow[i] = nullptr;
    }

    for (int k0 = 0; k0 < K; k0 += BK) {
        // stage A tile (gathered rows), split hi/lo
        #pragma unroll
        for (int i = 0; i < 4; i++) {
            float4 v = make_float4(0.f, 0.f, 0.f, 0.f);
            if (arow[i]) v = *(const float4*)(arow[i] + k0 + acol[i]);
            int o = ar[i] * (BK + APAD) + acol[i];
            cvtstore4(Ah + o, Al + o, v);
        }
        // stage B tile (row-major [k][n]), split hi/lo
        #pragma unroll
        for (int i = 0; i < 4; i++) {
            int id = tid + i * 256;
            int kk = id >> 5;
            int n  = (id & 31) * 4;
            float4 v = *(const float4*)(Bp + (size_t)(k0 + kk) * N + n);
            int o = kk * (BN + BPAD) + n;
            cvtstore4(Bh + o, Bl + o, v);
        }
        __syncthreads();

        #pragma unroll
        for (int ks = 0; ks < 2; ks++) {
            int kk = ks * 16;
            uint32_t ah[4][4], al[4][4];
            #pragma unroll
            for (int mt = 0; mt < 4; mt++) {
                int row = wm + mt * 16 + (lane & 15);
                int col = kk + ((lane >> 4) << 3);
                ldm4(ah[mt], Ah + row * (BK + APAD) + col);
                ldm4(al[mt], Al + row * (BK + APAD) + col);
            }
            uint32_t bh[2][4], bl[2][4];
            #pragma unroll
            for (int np = 0; np < 2; np++) {
                int row = kk + (lane & 15);
                int col = wn + np * 16 + ((lane >> 4) << 3);
                ldm4t(bh[np], Bh + row * (BN + BPAD) + col);
                ldm4t(bl[np], Bl + row * (BN + BPAD) + col);
            }
            #pragma unroll
            for (int mt = 0; mt < 4; mt++)
                #pragma unroll
                for (int nt = 0; nt < 4; nt++) {
                    const uint32_t* bhp = &bh[nt >> 1][(nt & 1) * 2];
                    const uint32_t* blp = &bl[nt >> 1][(nt & 1) * 2];
                    mma16816(acc[mt][nt], ah[mt], bhp);   // hi*hi
                    mma16816(acc[mt][nt], ah[mt], blp);   // hi*lo
                    mma16816(acc[mt][nt], al[mt], bhp);   // lo*hi  (lo*lo dropped ~2^-18)
                }
        }
        __syncthreads();
    }

    // epilogue: C frag = (row lane>>2 / +8, col (lane&3)*2)
    #pragma unroll
    for (int mt = 0; mt < 4; mt++) {
        #pragma unroll
        for (int nt = 0; nt < 4; nt++) {
            int r = m0blk + wm + mt * 16 + (lane >> 2);
            int c = (int)blockIdx.x * BN + wn + nt * 8 + (lane & 3) * 2;
            if (r < Me) {
                float2 v; v.x = acc[mt][nt][0]; v.y = acc[mt][nt][1];
                *(float2*)&C[(size_t)(offe + r) * N + c] = v;
            }
            if (r + 8 < Me) {
                float2 v; v.x = acc[mt][nt][2]; v.y = acc[mt][nt][3];
                *(float2*)&C[(size_t)(offe + r + 8) * N + c] = v;
            }
        }
    }
}

__global__ void swiglu_kernel() {
    size_t i = (size_t)blockIdx.x * blockDim.x + threadIdx.x;  // float4 index
    float4 g = ((const float4*)g_hg)[i];
    float4 u = ((const float4*)g_hu)[i];
    float4 r;
    r.x = (g.x / (1.f + __expf(-g.x))) * u.x;
    r.y = (g.y / (1.f + __expf(-g.y))) * u.y;
    r.z = (g.z / (1.f + __expf(-g.z))) * u.z;
    r.w = (g.w / (1.f + __expf(-g.w))) * u.w;
    ((float4*)g_h)[i] = r;
}

// out[t] = w0 * y[row0] + w1 * y[row1]  (fully covers out; no init needed)
__global__ void combine_kernel(float* __restrict__ out) {
    int t = blockIdx.x;
    int v0 = g_asg[t * 2 + 0], v1 = g_asg[t * 2 + 1];
    float w0 = g_wt[t * 2 + 0], w1 = g_wt[t * 2 + 1];
    int r0 = g_off[v0 >> 12] + (v0 & 4095);
    int r1 = g_off[v1 >> 12] + (v1 & 4095);
    const float4* y0 = (const float4*)(g_y + (size_t)r0 * HH);
    const float4* y1 = (const float4*)(g_y + (size_t)r1 * HH);
    float4* o = (float4*)(out + (size_t)t * HH);
    for (int i = threadIdx.x; i < HH / 4; i += blockDim.x) {
        float4 a = y0[i], b = y1[i], r;
        r.x = w0 * a.x + w1 * b.x;
        r.y = w0 * a.y + w1 * b.y;
        r.z = w0 * a.z + w1 * b.z;
        r.w = w0 * a.w + w1 * b.w;
        o[i] = r;
    }
}

// ---------------- launch ------------------------------------------------------
extern "C" void kernel_launch(void* const* d_in, const int* in_sizes, int n_in,
                              void* d_out, int out_size)
{
    (void)in_sizes; (void)n_in; (void)out_size;
    const float* x  = (const float*)d_in[0];   // hidden_states [T, H]
    const float* gw = (const float*)d_in[1];   // gate_w [H, E]
    const float* wg = (const float*)d_in[2];   // w_gate [E, H, I]
    const float* wu = (const float*)d_in[3];   // w_up   [E, H, I]
    const float* wd = (const float*)d_in[4];   // w_down [E, I, H]
    float* out = (float*)d_out;

    float *hg, *hu, *h, *y;
    cudaGetSymbolAddress((void**)&hg, g_hg);
    cudaGetSymbolAddress((void**)&hu, g_hu);
    cudaGetSymbolAddress((void**)&h,  g_h);
    cudaGetSymbolAddress((void**)&y,  g_y);

    zero_cnt_kernel<<<1, 32>>>();
    router_kernel<<<TT, 256>>>(x, gw);
    prefix_kernel<<<1, 1>>>();

    dim3 g1(II / BN, TT / BM, EE);   // (32, 32, 8) — most blocks early-exit
    gemm_kernel<true><<<g1, 256>>>(x, wg, hg, HH, II);
    gemm_kernel<true><<<g1, 256>>>(x, wu, hu, HH, II);

    swiglu_kernel<<<(NASG * (size_t)II / 4) / 256, 256>>>();

    dim3 g2(HH / BN, TT / BM, EE);   // (16, 32, 8)
    gemm_kernel<false><<<g2, 256>>>(h, wd, y, II, HH);

    combine_kernel<<<TT, 256>>>(out);
}

// round 12
// speedup vs baseline: 1.5907x; 1.5907x over previous
#include <cuda_runtime.h>
#include <cuda_bf16.h>
#include <cstdint>

// MoELayer: B=2,S=2048,H=2048,I=4096,E=8, top-2
#define TT 4096
#define HH 2048
#define II 4096
#define EE 8
#define NASG (2*TT)

#define BM 128
#define BN 128
#define BK 32
#define AS 40    // A smem row stride (elems): 80B, conflict-free, 8B-aligned
#define BS 136   // B smem row stride (elems): 272B, conflict-free, 8B-aligned

// smem stage layout (bf16 elems): Ah 128*40=5120 | Al 5120 | Bh 32*136=4352 | Bl 4352
#define S_AL 5120
#define S_BH 10240
#define S_BL 14592
#define STAGE 18944
#define SMEMB (STAGE * 2 * 2)   // 2 stages * 2 bytes = 75776 B

// ---------------- static device scratch --------------------------------------
__device__ int   g_cnt[EE];
__device__ int   g_off[EE];
__device__ int   g_tok[EE * TT];
__device__ int   g_asg[TT * 2];
__device__ float g_wt[TT * 2];

__device__ __nv_bfloat16 g_xh[(size_t)TT * HH], g_xl[(size_t)TT * HH];
__device__ __nv_bfloat16 g_wgh[(size_t)EE * HH * II], g_wgl[(size_t)EE * HH * II];
__device__ __nv_bfloat16 g_wuh[(size_t)EE * HH * II], g_wul[(size_t)EE * HH * II];
__device__ __nv_bfloat16 g_wdh[(size_t)EE * II * HH], g_wdl[(size_t)EE * II * HH];
__device__ float         g_hg[(size_t)NASG * II], g_hu[(size_t)NASG * II];
__device__ __nv_bfloat16 g_hh[(size_t)NASG * II], g_hl[(size_t)NASG * II];
__device__ float         g_y[(size_t)NASG * HH];

// ---------------- helpers ----------------------------------------------------
__device__ __forceinline__ void ldm4(uint32_t* r, const __nv_bfloat16* p) {
    uint32_t a = (uint32_t)__cvta_generic_to_shared(p);
    asm volatile("ldmatrix.sync.aligned.m8n8.x4.shared.b16 {%0,%1,%2,%3}, [%4];"
                 : "=r"(r[0]), "=r"(r[1]), "=r"(r[2]), "=r"(r[3]) : "r"(a));
}
__device__ __forceinline__ void ldm4t(uint32_t* r, const __nv_bfloat16* p) {
    uint32_t a = (uint32_t)__cvta_generic_to_shared(p);
    asm volatile("ldmatrix.sync.aligned.m8n8.x4.trans.shared.b16 {%0,%1,%2,%3}, [%4];"
                 : "=r"(r[0]), "=r"(r[1]), "=r"(r[2]), "=r"(r[3]) : "r"(a));
}
__device__ __forceinline__ void mma16816(float* c, const uint32_t* a, const uint32_t* b) {
    asm volatile("mma.sync.aligned.m16n8k16.row.col.f32.bf16.bf16.f32 "
                 "{%0,%1,%2,%3},{%4,%5,%6,%7},{%8,%9},{%0,%1,%2,%3};"
                 : "+f"(c[0]), "+f"(c[1]), "+f"(c[2]), "+f"(c[3])
                 : "r"(a[0]), "r"(a[1]), "r"(a[2]), "r"(a[3]), "r"(b[0]), "r"(b[1]));
}
__device__ __forceinline__ void cpa8(__nv_bfloat16* dst, const __nv_bfloat16* src, bool v) {
    uint32_t d = (uint32_t)__cvta_generic_to_shared(dst);
    int sz = v ? 8 : 0;
    asm volatile("cp.async.ca.shared.global [%0], [%1], 8, %2;\n"
                 :: "r"(d), "l"(src), "r"(sz));
}
__device__ __forceinline__ void splitpack(float4 v, uint2& H, uint2& L) {
    __nv_bfloat16 h0 = __float2bfloat16_rn(v.x), h1 = __float2bfloat16_rn(v.y);
    __nv_bfloat16 h2 = __float2bfloat16_rn(v.z), h3 = __float2bfloat16_rn(v.w);
    __nv_bfloat16 l0 = __float2bfloat16_rn(v.x - __bfloat162float(h0));
    __nv_bfloat16 l1 = __float2bfloat16_rn(v.y - __bfloat162float(h1));
    __nv_bfloat16 l2 = __float2bfloat16_rn(v.z - __bfloat162float(h2));
    __nv_bfloat16 l3 = __float2bfloat16_rn(v.w - __bfloat162float(h3));
    __nv_bfloat162 a, b;
    a.x = h0; a.y = h1; b.x = h2; b.y = h3;
    H.x = *(uint32_t*)&a; H.y = *(uint32_t*)&b;
    a.x = l0; a.y = l1; b.x = l2; b.y = l3;
    L.x = *(uint32_t*)&a; L.y = *(uint32_t*)&b;
}

// ---------------- small kernels ----------------------------------------------
__global__ void zero_cnt_kernel() { if (threadIdx.x < EE) g_cnt[threadIdx.x] = 0; }

__global__ void split_kernel(const float4* __restrict__ src,
                             uint2* __restrict__ hi, uint2* __restrict__ lo) {
    size_t i = (size_t)blockIdx.x * blockDim.x + threadIdx.x;
    uint2 H, L;
    splitpack(src[i], H, L);
    hi[i] = H; lo[i] = L;
}

__global__ void router_kernel(const float* __restrict__ x, const float* __restrict__ gw) {
    int t = blockIdx.x;
    const float* xr = x + (size_t)t * HH;
    __shared__ float slog[EE];
    int warp = threadIdx.x >> 5, lane = threadIdx.x & 31;
    float s = 0.f;
    for (int h = lane; h < HH; h += 32) s += xr[h] * gw[h * EE + warp];
    #pragma unroll
    for (int o = 16; o; o >>= 1) s += __shfl_xor_sync(0xffffffffu, s, o);
    if (lane == 0) slog[warp] = s;
    __syncthreads();
    if (threadIdx.x == 0) {
        float mx = slog[0];
        #pragma unroll
        for (int e = 1; e < EE; e++) mx = fmaxf(mx, slog[e]);
        float p[EE];
        #pragma unroll
        for (int e = 0; e < EE; e++) p[e] = __expf(slog[e] - mx);
        int i0 = 0;
        #pragma unroll
        for (int e = 1; e < EE; e++) if (p[e] > p[i0]) i0 = e;
        int i1 = (i0 == 0) ? 1 : 0;
        #pragma unroll
        for (int e = 0; e < EE; e++) if (e != i0 && p[e] > p[i1]) i1 = e;
        float w0 = p[i0], w1 = p[i1], ws = w0 + w1;
        w0 /= ws; w1 /= ws;
        int s0 = atomicAdd(&g_cnt[i0], 1);
        int s1 = atomicAdd(&g_cnt[i1], 1);
        g_tok[i0 * TT + s0] = t;
        g_tok[i1 * TT + s1] = t;
        g_asg[t * 2 + 0] = (i0 << 12) | s0;  g_wt[t * 2 + 0] = w0;
        g_asg[t * 2 + 1] = (i1 << 12) | s1;  g_wt[t * 2 + 1] = w1;
    }
}

__global__ void prefix_kernel() {
    if (threadIdx.x == 0) {
        int a = 0;
        #pragma unroll
        for (int e = 0; e < EE; e++) { g_off[e] = a; a += g_cnt[e]; }
    }
}

// ---------------- pipelined split-bf16 GEMM ----------------------------------
// C[offe+m][n] = A_rows @ B[e];  A/B pre-split into bf16 hi/lo planes.
// grid.x spans [0,nx0) -> (Bh0,Bl0,C0), [nx0,2*nx0) -> (Bh1,Bl1,C1)  (fused gate/up)
template <bool GATHER>
__global__ __launch_bounds__(256, 2) void gemm2(
    const __nv_bfloat16* __restrict__ Ahg, const __nv_bfloat16* __restrict__ Alg,
    const __nv_bfloat16* __restrict__ Bh0, const __nv_bfloat16* __restrict__ Bl0, float* __restrict__ C0,
    const __nv_bfloat16* __restrict__ Bh1, const __nv_bfloat16* __restrict__ Bl1, float* __restrict__ C1,
    int K, int N, int nx0)
{
    int e = blockIdx.z;
    int Me = g_cnt[e];
    int m0 = blockIdx.y * BM;
    if (m0 >= Me) return;
    int offe = g_off[e];

    int bx = blockIdx.x;
    const __nv_bfloat16 *Bh, *Bl; float* C;
    if (bx < nx0) { Bh = Bh0; Bl = Bl0; C = C0; }
    else          { bx -= nx0; Bh = Bh1; Bl = Bl1; C = C1; }
    Bh += (size_t)e * K * N + (size_t)bx * BN;
    Bl += (size_t)e * K * N + (size_t)bx * BN;

    extern __shared__ __nv_bfloat16 sm[];

    int tid = threadIdx.x, lane = tid & 31, warp = tid >> 5;
    int wm = (warp & 1) * 64, wn = (warp >> 1) * 32;

    // A row element-offsets (32-bit; max 8192*4096 fits)
    int aoff[4]; bool av[4];
    #pragma unroll
    for (int i = 0; i < 4; i++) {
        int id = tid + i * 256;
        int gm = m0 + (id >> 3);
        av[i] = gm < Me;
        int row = 0;
        if (av[i]) row = GATHER ? g_tok[e * TT + gm] : (offe + gm);
        aoff[i] = row * K;
    }

    float acc[4][4][4];
    #pragma unroll
    for (int mt = 0; mt < 4; mt++)
        #pragma unroll
        for (int nt = 0; nt < 4; nt++)
            #pragma unroll
            for (int i = 0; i < 4; i++) acc[mt][nt][i] = 0.f;

    auto issue = [&](int k0, int s) {
        __nv_bfloat16* base = sm + s * STAGE;
        #pragma unroll
        for (int i = 0; i < 4; i++) {
            int id = tid + i * 256;
            int r = id >> 3, c = (id & 7) * 4;
            int so = r * AS + c;
            cpa8(base + so,        Ahg + aoff[i] + k0 + c, av[i]);
            cpa8(base + S_AL + so, Alg + aoff[i] + k0 + c, av[i]);
        }
        #pragma unroll
        for (int i = 0; i < 4; i++) {
            int id = tid + i * 256;
            int kk = id >> 5, n = (id & 31) * 4;
            int so = kk * BS + n;
            size_t go = (size_t)(k0 + kk) * N + n;
            cpa8(base + S_BH + so, Bh + go, true);
            cpa8(base + S_BL + so, Bl + go, true);
        }
        asm volatile("cp.async.commit_group;\n" ::);
    };

    issue(0, 0);
    int nk = K / BK;
    for (int kt = 0; kt < nk; kt++) {
        int s = kt & 1;
        asm volatile("cp.async.wait_group 0;\n" ::: "memory");
        __syncthreads();
        if (kt + 1 < nk) issue((kt + 1) * BK, s ^ 1);

        __nv_bfloat16* base = sm + s * STAGE;
        #pragma unroll
        for (int ks = 0; ks < 2; ks++) {
            int kk = ks * 16;
            uint32_t ah[4][4], al[4][4];
            #pragma unroll
            for (int mt = 0; mt < 4; mt++) {
                int row = wm + mt * 16 + (lane & 15);
                int col = kk + ((lane >> 4) << 3);
                ldm4(ah[mt], base + row * AS + col);
                ldm4(al[mt], base + S_AL + row * AS + col);
            }
            uint32_t bh[2][4], bl[2][4];
            #pragma unroll
            for (int np = 0; np < 2; np++) {
                int row = kk + (lane & 15);
                int col = wn + np * 16 + ((lane >> 4) << 3);
                ldm4t(bh[np], base + S_BH + row * BS + col);
                ldm4t(bl[np], base + S_BL + row * BS + col);
            }
            #pragma unroll
            for (int mt = 0; mt < 4; mt++)
                #pragma unroll
                for (int nt = 0; nt < 4; nt++) {
                    const uint32_t* bhp = &bh[nt >> 1][(nt & 1) * 2];
                    const uint32_t* blp = &bl[nt >> 1][(nt & 1) * 2];
                    mma16816(acc[mt][nt], ah[mt], bhp);
                    mma16816(acc[mt][nt], ah[mt], blp);
                    mma16816(acc[mt][nt], al[mt], bhp);
                }
        }
        __syncthreads();
    }

    #pragma unroll
    for (int mt = 0; mt < 4; mt++) {
        #pragma unroll
        for (int nt = 0; nt < 4; nt++) {
            int r = m0 + wm + mt * 16 + (lane >> 2);
            int c = bx * BN + wn + nt * 8 + (lane & 3) * 2;
            if (r < Me) {
                float2 v; v.x = acc[mt][nt][0]; v.y = acc[mt][nt][1];
                *(float2*)&C[(size_t)(offe + r) * N + c] = v;
            }
            if (r + 8 < Me) {
                float2 v; v.x = acc[mt][nt][2]; v.y = acc[mt][nt][3];
                *(float2*)&C[(size_t)(offe + r + 8) * N + c] = v;
            }
        }
    }
}

__global__ void swiglu_kernel() {
    size_t i = (size_t)blockIdx.x * blockDim.x + threadIdx.x;  // float4 index
    float4 g = ((const float4*)g_hg)[i];
    float4 u = ((const float4*)g_hu)[i];
    float4 r;
    r.x = (g.x / (1.f + __expf(-g.x))) * u.x;
    r.y = (g.y / (1.f + __expf(-g.y))) * u.y;
    r.z = (g.z / (1.f + __expf(-g.z))) * u.z;
    r.w = (g.w / (1.f + __expf(-g.w))) * u.w;
    uint2 H, L;
    splitpack(r, H, L);
    ((uint2*)g_hh)[i] = H;
    ((uint2*)g_hl)[i] = L;
}

__global__ void combine_kernel(float* __restrict__ out) {
    int t = blockIdx.x;
    int v0 = g_asg[t * 2 + 0], v1 = g_asg[t * 2 + 1];
    float w0 = g_wt[t * 2 + 0], w1 = g_wt[t * 2 + 1];
    int r0 = g_off[v0 >> 12] + (v0 & 4095);
    int r1 = g_off[v1 >> 12] + (v1 & 4095);
    const float4* y0 = (const float4*)(g_y + (size_t)r0 * HH);
    const float4* y1 = (const float4*)(g_y + (size_t)r1 * HH);
    float4* o = (float4*)(out + (size_t)t * HH);
    for (int i = threadIdx.x; i < HH / 4; i += blockDim.x) {
        float4 a = y0[i], b = y1[i], r;
        r.x = w0 * a.x + w1 * b.x;
        r.y = w0 * a.y + w1 * b.y;
        r.z = w0 * a.z + w1 * b.z;
        r.w = w0 * a.w + w1 * b.w;
        o[i] = r;
    }
}

// ---------------- launch ------------------------------------------------------
extern "C" void kernel_launch(void* const* d_in, const int* in_sizes, int n_in,
                              void* d_out, int out_size)
{
    (void)in_sizes; (void)n_in; (void)out_size;
    const float* x  = (const float*)d_in[0];
    const float* gw = (const float*)d_in[1];
    const float* wg = (const float*)d_in[2];
    const float* wu = (const float*)d_in[3];
    const float* wd = (const float*)d_in[4];
    float* out = (float*)d_out;

    void *xh, *xl, *wgh, *wgl, *wuh, *wul, *wdh, *wdl, *hg, *hu, *hh, *hl, *y;
    cudaGetSymbolAddress(&xh, g_xh);   cudaGetSymbolAddress(&xl, g_xl);
    cudaGetSymbolAddress(&wgh, g_wgh); cudaGetSymbolAddress(&wgl, g_wgl);
    cudaGetSymbolAddress(&wuh, g_wuh); cudaGetSymbolAddress(&wul, g_wul);
    cudaGetSymbolAddress(&wdh, g_wdh); cudaGetSymbolAddress(&wdl, g_wdl);
    cudaGetSymbolAddress(&hg, g_hg);   cudaGetSymbolAddress(&hu, g_hu);
    cudaGetSymbolAddress(&hh, g_hh);   cudaGetSymbolAddress(&hl, g_hl);
    cudaGetSymbolAddress(&y, g_y);

    cudaFuncSetAttribute(gemm2<true>,  cudaFuncAttributeMaxDynamicSharedMemorySize, SMEMB);
    cudaFuncSetAttribute(gemm2<false>, cudaFuncAttributeMaxDynamicSharedMemorySize, SMEMB);

    zero_cnt_kernel<<<1, 32>>>();
    router_kernel<<<TT, 256>>>(x, gw);
    prefix_kernel<<<1, 1>>>();

    // pre-split operands into bf16 hi/lo planes
    int wblk = (EE * HH * (II / 4)) / 256;      // 65536
    split_kernel<<<wblk, 256>>>((const float4*)wg, (uint2*)wgh, (uint2*)wgl);
    split_kernel<<<wblk, 256>>>((const float4*)wu, (uint2*)wuh, (uint2*)wul);
    split_kernel<<<wblk, 256>>>((const float4*)wd, (uint2*)wdh, (uint2*)wdl);
    split_kernel<<<(TT * (HH / 4)) / 256, 256>>>((const float4*)x, (uint2*)xh, (uint2*)xl);

    // fused gate+up GEMM
    dim3 g1(2 * (II / BN), TT / BM, EE);        // (64, 32, 8)
    gemm2<true><<<g1, 256, SMEMB>>>(
        (const __nv_bfloat16*)xh, (const __nv_bfloat16*)xl,
        (const __nv_bfloat16*)wgh, (const __nv_bfloat16*)wgl, (float*)hg,
        (const __nv_bfloat16*)wuh, (const __nv_bfloat16*)wul, (float*)hu,
        HH, II, II / BN);

    swiglu_kernel<<<((size_t)NASG * II / 4) / 256, 256>>>();

    dim3 g2(HH / BN, TT / BM, EE);              // (16, 32, 8)
    gemm2<false><<<g2, 256, SMEMB>>>(
        (const __nv_bfloat16*)hh, (const __nv_bfloat16*)hl,
        (const __nv_bfloat16*)wdh, (const __nv_bfloat16*)wdl, (float*)y,
        (const __nv_bfloat16*)wdh, (const __nv_bfloat16*)wdl, (float*)y,
        II, HH, HH / BN);

    combine_kernel<<<TT, 256>>>(out);
}